// round 8
// baseline (speedup 1.0000x reference)
#include <cuda_runtime.h>

// ChannelDropout — persistent grid-stride, read-elided, pos-prefetched:
//   1184 blocks (148 SMs x 8 resident) x 256 thr, each block loops over ~15
//   rows (stride 1184). Exactly one wave: no wave transitions, no tail.
//   Next row's pos is prefetched one iteration ahead, so the kept-branch
//   resolves from a register and kept-row signal loads issue immediately.
//   Dropped rows (dist<=0.2 from center, ~10%) write zeros without reading.
//   MC keep-count: 4 warp ballots, no smem, no barriers.

#define DROPOUT2 0.04f   // 0.2^2
#define EPSILON  1e-8f
#define T4       750     // 3000 floats / 4
#define ROWS     (64 * 273)   // 17472
#define GRID     1184         // 148 * 8

__global__ __launch_bounds__(256, 8)
void fused_kernel(const float* __restrict__ sig,
                  const float2* __restrict__ pos2,
                  const float* __restrict__ center,
                  const float* __restrict__ mc,
                  float* __restrict__ out)
{
    const int tid  = threadIdx.x;
    const int lane = tid & 31;

    const int i0 = tid;
    const int i1 = tid + 256;
    const int i2 = tid + 512;
    const bool has2 = (i2 < T4);               // tid < 238

    const float cx = __ldg(&center[0]);
    const float cy = __ldg(&center[1]);

    int row = blockIdx.x;
    float2 p = __ldg(&pos2[row]);              // first row's position

    for (; row < ROWS; row += GRID) {
        // Prefetch next iteration's pos now (independent, hides under this row).
        const int nrow = row + GRID;
        float2 pn = (nrow < ROWS) ? __ldg(&pos2[nrow]) : make_float2(0.f, 0.f);

        float4* __restrict__ o4 = (float4*)(out) + (size_t)row * T4;

        const float dx = p.x - cx, dy = p.y - cy;
        const bool kept = (dx * dx + dy * dy) > DROPOUT2;

        if (!kept) {
            const float4 z = make_float4(0.f, 0.f, 0.f, 0.f);
            __stcs(&o4[i0], z);
            __stcs(&o4[i1], z);
            if (has2) __stcs(&o4[i2], z);
        } else {
            // Signal loads issue immediately — p is already in a register.
            const float4* __restrict__ s4 = (const float4*)(sig) + (size_t)row * T4;
            float4 v0 = __ldcs(&s4[i0]);
            float4 v1 = __ldcs(&s4[i1]);
            float4 v2 = has2 ? __ldcs(&s4[i2]) : make_float4(0.f, 0.f, 0.f, 0.f);

            // MC keep-count (warp-cooperative; mc is L1/L2-resident after wave 1).
            float ax, ay;
            ax = p.x - __ldg(&mc[2 * lane + 0]);
            ay = p.y - __ldg(&mc[2 * lane + 1]);
            const bool f0 = (ax * ax + ay * ay) > DROPOUT2;

            ax = p.x - __ldg(&mc[2 * (lane + 32) + 0]);
            ay = p.y - __ldg(&mc[2 * (lane + 32) + 1]);
            const bool f1 = (ax * ax + ay * ay) > DROPOUT2;

            ax = p.x - __ldg(&mc[2 * (lane + 64) + 0]);
            ay = p.y - __ldg(&mc[2 * (lane + 64) + 1]);
            const bool f2 = (ax * ax + ay * ay) > DROPOUT2;

            bool f3 = false;
            if (lane < 4) {
                ax = p.x - __ldg(&mc[2 * (lane + 96) + 0]);
                ay = p.y - __ldg(&mc[2 * (lane + 96) + 1]);
                f3 = (ax * ax + ay * ay) > DROPOUT2;
            }

            const unsigned b0 = __ballot_sync(0xFFFFFFFFu, f0);
            const unsigned b1 = __ballot_sync(0xFFFFFFFFu, f1);
            const unsigned b2 = __ballot_sync(0xFFFFFFFFu, f2);
            const unsigned b3 = __ballot_sync(0xFFFFFFFFu, f3);

            const int cnt = __popc(b0) + __popc(b1) + __popc(b2) + __popc(b3 & 0xFu);

            const float proba = __int2float_rn(cnt) * 0.01f;
            const float scale = 1.0f / (EPSILON + proba);

            v0.x *= scale; v0.y *= scale; v0.z *= scale; v0.w *= scale;
            v1.x *= scale; v1.y *= scale; v1.z *= scale; v1.w *= scale;
            __stcs(&o4[i0], v0);
            __stcs(&o4[i1], v1);
            if (has2) {
                v2.x *= scale; v2.y *= scale; v2.z *= scale; v2.w *= scale;
                __stcs(&o4[i2], v2);
            }
        }

        p = pn;
    }
}

extern "C" void kernel_launch(void* const* d_in, const int* in_sizes, int n_in,
                              void* d_out, int out_size)
{
    const float* sig    = (const float*)d_in[0];   // (64, 273, 3000) f32
    const float2* pos2  = (const float2*)d_in[1];  // (64, 273, 2)    f32
    const float* center = (const float*)d_in[2];   // (2,)            f32
    const float* mc     = (const float*)d_in[3];   // (100, 2)        f32
    float* out          = (float*)d_out;

    fused_kernel<<<GRID, 256>>>(sig, pos2, center, mc, out);
}

// round 9
// speedup vs baseline: 1.1399x; 1.1399x over previous
#include <cuda_runtime.h>

// ChannelDropout — block-per-row, read-elided, deep-MLP variant:
//   One block of 128 threads per row (17472 rows x 3000 f32 = 750 float4).
//   Each thread front-batches 6 LDG.128 (5 unconditional + 1 predicated:
//   128*6=768 >= 750) -> MLP_p1 ~6, double R7's depth, 16 blocks/SM.
//   kept(row) from pos+center computed first; dropped rows (~10%) write
//   zeros without reading signal. MC keep-count via 4 warp ballots.

#define DROPOUT2 0.04f   // 0.2^2
#define EPSILON  1e-8f
#define T4       750     // 3000 floats / 4
#define ROWS     (64 * 273)   // 17472

__global__ __launch_bounds__(128, 16)
void fused_kernel(const float* __restrict__ sig,
                  const float2* __restrict__ pos2,
                  const float* __restrict__ center,
                  const float* __restrict__ mc,
                  float* __restrict__ out)
{
    const int row  = blockIdx.x;
    const int tid  = threadIdx.x;      // 0..127
    const int lane = tid & 31;

    float4* __restrict__ o4 = (float4*)(out) + (size_t)row * T4;

    const int i0 = tid;
    const int i1 = tid + 128;
    const int i2 = tid + 256;
    const int i3 = tid + 384;
    const int i4 = tid + 512;          // max 639 < 750, always valid
    const int i5 = tid + 640;
    const bool has5 = (i5 < T4);       // tid < 110

    // --- kept check: only pos + center (block-uniform branch) ---
    const float2 p  = __ldg(&pos2[row]);
    const float cx = __ldg(&center[0]);
    const float cy = __ldg(&center[1]);

    const float dx = p.x - cx, dy = p.y - cy;
    const bool kept = (dx * dx + dy * dy) > DROPOUT2;

    if (!kept) {
        const float4 z = make_float4(0.f, 0.f, 0.f, 0.f);
        __stcs(&o4[i0], z);
        __stcs(&o4[i1], z);
        __stcs(&o4[i2], z);
        __stcs(&o4[i3], z);
        __stcs(&o4[i4], z);
        if (has5) __stcs(&o4[i5], z);
        return;
    }

    // --- kept row: front-batch 6 signal loads ---
    const float4* __restrict__ s4 = (const float4*)(sig) + (size_t)row * T4;
    float4 v0 = __ldcs(&s4[i0]);
    float4 v1 = __ldcs(&s4[i1]);
    float4 v2 = __ldcs(&s4[i2]);
    float4 v3 = __ldcs(&s4[i3]);
    float4 v4 = __ldcs(&s4[i4]);
    float4 v5 = has5 ? __ldcs(&s4[i5]) : make_float4(0.f, 0.f, 0.f, 0.f);

    // --- MC keep-count, warp-cooperative (hides under in-flight loads) ---
    float ax, ay;
    ax = p.x - __ldg(&mc[2 * lane + 0]);
    ay = p.y - __ldg(&mc[2 * lane + 1]);
    const bool f0 = (ax * ax + ay * ay) > DROPOUT2;

    ax = p.x - __ldg(&mc[2 * (lane + 32) + 0]);
    ay = p.y - __ldg(&mc[2 * (lane + 32) + 1]);
    const bool f1 = (ax * ax + ay * ay) > DROPOUT2;

    ax = p.x - __ldg(&mc[2 * (lane + 64) + 0]);
    ay = p.y - __ldg(&mc[2 * (lane + 64) + 1]);
    const bool f2 = (ax * ax + ay * ay) > DROPOUT2;

    bool f3 = false;
    if (lane < 4) {
        ax = p.x - __ldg(&mc[2 * (lane + 96) + 0]);
        ay = p.y - __ldg(&mc[2 * (lane + 96) + 1]);
        f3 = (ax * ax + ay * ay) > DROPOUT2;
    }

    const unsigned b0 = __ballot_sync(0xFFFFFFFFu, f0);
    const unsigned b1 = __ballot_sync(0xFFFFFFFFu, f1);
    const unsigned b2 = __ballot_sync(0xFFFFFFFFu, f2);
    const unsigned b3 = __ballot_sync(0xFFFFFFFFu, f3);

    const int cnt = __popc(b0) + __popc(b1) + __popc(b2) + __popc(b3 & 0xFu);

    const float proba = __int2float_rn(cnt) * 0.01f;
    const float scale = 1.0f / (EPSILON + proba);

    // --- scale + streaming stores ---
    v0.x *= scale; v0.y *= scale; v0.z *= scale; v0.w *= scale;
    v1.x *= scale; v1.y *= scale; v1.z *= scale; v1.w *= scale;
    v2.x *= scale; v2.y *= scale; v2.z *= scale; v2.w *= scale;
    v3.x *= scale; v3.y *= scale; v3.z *= scale; v3.w *= scale;
    v4.x *= scale; v4.y *= scale; v4.z *= scale; v4.w *= scale;
    __stcs(&o4[i0], v0);
    __stcs(&o4[i1], v1);
    __stcs(&o4[i2], v2);
    __stcs(&o4[i3], v3);
    __stcs(&o4[i4], v4);
    if (has5) {
        v5.x *= scale; v5.y *= scale; v5.z *= scale; v5.w *= scale;
        __stcs(&o4[i5], v5);
    }
}

extern "C" void kernel_launch(void* const* d_in, const int* in_sizes, int n_in,
                              void* d_out, int out_size)
{
    const float* sig    = (const float*)d_in[0];   // (64, 273, 3000) f32
    const float2* pos2  = (const float2*)d_in[1];  // (64, 273, 2)    f32
    const float* center = (const float*)d_in[2];   // (2,)            f32
    const float* mc     = (const float*)d_in[3];   // (100, 2)        f32
    float* out          = (float*)d_out;

    fused_kernel<<<ROWS, 128>>>(sig, pos2, center, mc, out);
}